// round 16
// baseline (speedup 1.0000x reference)
#include <cuda_runtime.h>
#include <cuda_fp16.h>
#include <math.h>
#include <stdint.h>

#define S_LEN   8192
#define BATCH   4
#define DMODEL  1024
#define NROWS   (BATCH * S_LEN)   // 32768
#define NHEADS  16
#define DHEAD   64

// Scratch (device globals: allocation-free per harness rules)
__device__ __half g_hqf[(size_t)NROWS * DMODEL];  // fp16 Q features (token-major)
__device__ __half g_hkt[(size_t)NROWS * DMODEL];  // fp16 K features TRANSPOSED [b*1024+feat][s]
__device__ __half g_hvt[(size_t)NROWS * DMODEL];  // fp16 V features TRANSPOSED
__device__ __half g_hq[(size_t)NROWS * DMODEL];   // fp16-rounded inputs
__device__ __half g_hk[(size_t)NROWS * DMODEL];
__device__ __half g_hv[(size_t)NROWS * DMODEL];
__device__ __half g_hattn[(size_t)NROWS * DMODEL];
__device__ __half g_hw[4][DMODEL * DMODEL];       // fp16-rounded weights
__device__ float  g_kv[BATCH * NHEADS * DHEAD * DHEAD];   // [b,h,dv,dk]
__device__ float  g_ksum[BATCH * NHEADS * DHEAD];

// ---------------------------------------------------------------------------
// helpers
// ---------------------------------------------------------------------------
__device__ __forceinline__ void mma_fp16(float* c, const unsigned* a, const unsigned* b) {
    asm volatile(
        "mma.sync.aligned.m16n8k16.row.col.f32.f16.f16.f32 "
        "{%0,%1,%2,%3}, {%4,%5,%6,%7}, {%8,%9}, {%0,%1,%2,%3};"
        : "+f"(c[0]), "+f"(c[1]), "+f"(c[2]), "+f"(c[3])
        : "r"(a[0]), "r"(a[1]), "r"(a[2]), "r"(a[3]), "r"(b[0]), "r"(b[1]));
}

__device__ __forceinline__ void cp_async16(unsigned smem_addr, const void* gptr) {
    asm volatile("cp.async.cg.shared.global [%0], [%1], 16;"
                 :: "r"(smem_addr), "l"(gptr));
}
__device__ __forceinline__ void cp_commit() {
    asm volatile("cp.async.commit_group;");
}
template <int N>
__device__ __forceinline__ void cp_wait() {
    asm volatile("cp.async.wait_group %0;" :: "n"(N));
}

// ---------------------------------------------------------------------------
// Merged fp16 rounding passes (blockIdx.y selects tensor)
// ---------------------------------------------------------------------------
__global__ void round3_fp16_kernel(const float* __restrict__ i0, __half* __restrict__ o0,
                                   const float* __restrict__ i1, __half* __restrict__ o1,
                                   const float* __restrict__ i2, __half* __restrict__ o2,
                                   int n4) {
    int i = blockIdx.x * blockDim.x + threadIdx.x;
    if (i >= n4) return;
    const float* in;
    __half* out;
    switch (blockIdx.y) {
        case 0:  in = i0; out = o0; break;
        case 1:  in = i1; out = o1; break;
        default: in = i2; out = o2; break;
    }
    float4 v = ((const float4*)in)[i];
    __half2* o = (__half2*)(out + (size_t)i * 4);
    o[0] = __floats2half2_rn(v.x, v.y);
    o[1] = __floats2half2_rn(v.z, v.w);
}

__global__ void round4_fp16_kernel(const float* __restrict__ i0, __half* __restrict__ o0,
                                   const float* __restrict__ i1, __half* __restrict__ o1,
                                   const float* __restrict__ i2, __half* __restrict__ o2,
                                   const float* __restrict__ i3, __half* __restrict__ o3,
                                   int n4) {
    int i = blockIdx.x * blockDim.x + threadIdx.x;
    if (i >= n4) return;
    const float* in;
    __half* out;
    switch (blockIdx.y) {
        case 0:  in = i0; out = o0; break;
        case 1:  in = i1; out = o1; break;
        case 2:  in = i2; out = o2; break;
        default: in = i3; out = o3; break;
    }
    float4 v = ((const float4*)in)[i];
    __half2* o = (__half2*)(out + (size_t)i * 4);
    o[0] = __floats2half2_rn(v.x, v.y);
    o[1] = __floats2half2_rn(v.z, v.w);
}

__global__ void zero_kernel(float* p, int n) {
    int i = blockIdx.x * blockDim.x + threadIdx.x;
    if (i < n) p[i] = 0.0f;
}

// ---------------------------------------------------------------------------
// fp16 GEMM: C = A @ W^T + bias, optional elu+1.
// OUTMODE: 0 = fp32 token-major, 1 = fp16 token-major,
//          2 = fp16 TRANSPOSED: Ct[(b*1024 + col)][s], s contiguous
// 256 threads, 8 warps (2x4), warp tile 64x32.
// 4-stage cp.async pipeline, ONE barrier per k-chunk:
//   wait<2>; sync; fill(kt+3); commit; compute(kt)
// fill(kt+3) targets stage (kt-1)%4 whose readers finished compute(kt-1)
// before this barrier; wait<2> guarantees fill(kt) complete.
// ---------------------------------------------------------------------------
#define BM 128
#define BN 128
#define BKH 32                    // k halves per chunk
#define SPADH 48                  // halves per smem row (96B)
#define TILEH (BM * SPADH)        // 6144 halves = 12288 B
#define NSTAGE 4
#define GEMM_SMEM_BYTES (2 * NSTAGE * TILEH * 2)   // 98304 B
#define CPAD 130                  // halves per staging row

template <int EPI, int OUTMODE>
__global__ void __launch_bounds__(256, 2)
gemm_fp16_kernel(const __half* __restrict__ A, const __half* __restrict__ W,
                 const float* __restrict__ bias, void* __restrict__ Cv) {
    extern __shared__ __half sh[];            // [A0..A3, B0..B3]
    __half* Asm = sh;
    __half* Bsm = sh + NSTAGE * TILEH;

    const int tid  = threadIdx.x;
    const int lane = tid & 31;
    const int warp = tid >> 5;
    const int wm   = (warp & 1) * 64;
    const int wn   = (warp >> 1) * 32;
    const int m0   = blockIdx.y * BM;
    const int n0   = blockIdx.x * BN;
    const int g    = lane >> 2;
    const int tg   = lane & 3;

    unsigned sbase = (unsigned)__cvta_generic_to_shared(sh);

    float acc[4][4][4];
#pragma unroll
    for (int mt = 0; mt < 4; mt++)
#pragma unroll
        for (int nt = 0; nt < 4; nt++)
#pragma unroll
            for (int i = 0; i < 4; i++) acc[mt][nt][i] = 0.0f;

    const int r0  = tid >> 2;          // rows r0, r0+64
    const int kc  = (tid & 3) * 8;
    const __half* Ap = A + (size_t)(m0 + r0) * DMODEL + kc;
    const __half* Wp = W + (size_t)(n0 + r0) * DMODEL + kc;
    const unsigned a_d0 = sbase + (r0 * SPADH + kc) * 2;
    const unsigned a_d1 = sbase + ((r0 + 64) * SPADH + kc) * 2;
    const unsigned b_d0 = a_d0 + NSTAGE * TILEH * 2;
    const unsigned b_d1 = a_d1 + NSTAGE * TILEH * 2;

    const int NK = DMODEL / BKH;   // 32 chunks

    auto fill = [&](int c) {
        const unsigned so = (unsigned)(c % NSTAGE) * TILEH * 2;
        const __half* Apn = Ap + c * BKH;
        const __half* Wpn = Wp + c * BKH;
        cp_async16(a_d0 + so, Apn);
        cp_async16(a_d1 + so, Apn + (size_t)64 * DMODEL);
        cp_async16(b_d0 + so, Wpn);
        cp_async16(b_d1 + so, Wpn + (size_t)64 * DMODEL);
    };

    fill(0); cp_commit();
    fill(1); cp_commit();
    fill(2); cp_commit();

    for (int kt = 0; kt < NK; kt++) {
        cp_wait<2>();
        __syncthreads();

        if (kt + 3 < NK) fill(kt + 3);
        cp_commit();

        const int buf = kt % NSTAGE;
        const __half* Ab = Asm + buf * TILEH;
        const __half* Bb = Bsm + buf * TILEH;
#pragma unroll
        for (int ks = 0; ks < 2; ks++) {
            const int kk = ks * 16 + 4 * tg;
            unsigned a[4][4], b[4][2];
#pragma unroll
            for (int mt = 0; mt < 4; mt++) {
                int base = (wm + mt * 16 + g) * SPADH + kk;
                uint2 lo = *(const uint2*)&Ab[base];
                uint2 hi = *(const uint2*)&Ab[base + 8 * SPADH];
                a[mt][0] = lo.x; a[mt][1] = hi.x; a[mt][2] = lo.y; a[mt][3] = hi.y;
            }
#pragma unroll
            for (int nt = 0; nt < 4; nt++) {
                uint2 bb = *(const uint2*)&Bb[(wn + nt * 8 + g) * SPADH + kk];
                b[nt][0] = bb.x; b[nt][1] = bb.y;
            }
#pragma unroll
            for (int mt = 0; mt < 4; mt++)
#pragma unroll
                for (int nt = 0; nt < 4; nt++)
                    mma_fp16(acc[mt][nt], a[mt], b[nt]);
        }
    }

    if (OUTMODE == 2) __syncthreads();   // mainloop smem reads done before restaging

    // epilogue: bias + optional elu(x)+1
#pragma unroll
    for (int mt = 0; mt < 4; mt++) {
#pragma unroll
        for (int nt = 0; nt < 4; nt++) {
            int row = m0 + wm + mt * 16 + g;
            int col = n0 + wn + nt * 8 + 2 * tg;
            float bv0 = bias[col];
            float bv1 = bias[col + 1];
            float v00 = acc[mt][nt][0] + bv0;
            float v01 = acc[mt][nt][1] + bv1;
            float v10 = acc[mt][nt][2] + bv0;
            float v11 = acc[mt][nt][3] + bv1;
            if (EPI) {
                v00 = (v00 > 0.0f) ? v00 + 1.0f : expf(v00);
                v01 = (v01 > 0.0f) ? v01 + 1.0f : expf(v01);
                v10 = (v10 > 0.0f) ? v10 + 1.0f : expf(v10);
                v11 = (v11 > 0.0f) ? v11 + 1.0f : expf(v11);
            }
            if (OUTMODE == 0) {
                float* C = (float*)Cv;
                *(float2*)&C[(size_t)row * DMODEL + col]       = make_float2(v00, v01);
                *(float2*)&C[(size_t)(row + 8) * DMODEL + col] = make_float2(v10, v11);
            } else if (OUTMODE == 1) {
                __half* C = (__half*)Cv;
                *(__half2*)&C[(size_t)row * DMODEL + col]       = __floats2half2_rn(v00, v01);
                *(__half2*)&C[(size_t)(row + 8) * DMODEL + col] = __floats2half2_rn(v10, v11);
            } else {
                int lr = wm + mt * 16 + g;
                int lc = wn + nt * 8 + 2 * tg;
                *(__half2*)&sh[lr * CPAD + lc]       = __floats2half2_rn(v00, v01);
                *(__half2*)&sh[(lr + 8) * CPAD + lc] = __floats2half2_rn(v10, v11);
            }
        }
    }

    if (OUTMODE == 2) {
        __syncthreads();
        __half* Ct = (__half*)Cv;
        const int b    = m0 >> 13;        // m0 / 8192
        const int srow = m0 & 8191;
#pragma unroll
        for (int i = 0; i < 8; i++) {
            int slot = tid + 256 * i;
            int n  = slot & 127;
            int mb = slot >> 7;           // 0..15
            union { __half h[8]; uint4 u; } tmp;
#pragma unroll
            for (int j = 0; j < 8; j++)
                tmp.h[j] = sh[(mb * 8 + j) * CPAD + n];
            *(uint4*)&Ct[(size_t)(b * 1024 + n0 + n) * S_LEN + srow + mb * 8] = tmp.u;
        }
    }
}

// ---------------------------------------------------------------------------
// Tensor-core KV chain from TRANSPOSED features (R15 proven)
// ---------------------------------------------------------------------------
#define KVROWS 128
#define KVSTG 3
#define KVTILEH (KVROWS * SPADH)
#define NSPLIT 16

__global__ void __launch_bounds__(256)
kv_mma_kernel(const __half* __restrict__ Kt, const __half* __restrict__ Vt,
              float* __restrict__ kv, float* __restrict__ ksum) {
    __shared__ __half sh[KVSTG * KVTILEH];   // 36864 B

    const int bh = blockIdx.x;
    const int b  = bh >> 4;
    const int h  = bh & 15;
    const int s0 = blockIdx.y * (S_LEN / NSPLIT);
    const int tid  = threadIdx.x;
    const int lane = tid & 31;
    const int warp = tid >> 5;
    const int g    = lane >> 2;
    const int tg   = lane & 3;
    const int wm   = (warp & 3) * 16;
    const int wn   = (warp >> 2) * 32;

    const __half* VtB = Vt + (size_t)(b * 1024 + h * 64) * S_LEN + s0;
    const __half* KtB = Kt + (size_t)(b * 1024 + h * 64) * S_LEN + s0;

    unsigned sbase = (unsigned)__cvta_generic_to_shared(sh);

    const int fop  = tid >> 7;
    const int fidx = tid & 127;
    const __half* fb = fop ? KtB : VtB;

    auto fill = [&](int c) {
        const unsigned so = (unsigned)(c % KVSTG) * KVTILEH * 2;
#pragma unroll
        for (int i = 0; i < 2; i++) {
            int slot = fidx + 128 * i;
            int r  = slot >> 2;
            int kc = (slot & 3) * 8;
            cp_async16(sbase + so + ((fop * 64 + r) * SPADH + kc) * 2,
                       fb + (size_t)r * S_LEN + c * BKH + kc);
        }
    };

    float acc[4][4];
#pragma unroll
    for (int nt = 0; nt < 4; nt++)
#pragma unroll
        for (int i = 0; i < 4; i++) acc[nt][i] = 0.0f;

    const int NC = (S_LEN / NSPLIT) / BKH;   // 16 chunks
    fill(0); cp_commit();
    fill(1); cp_commit();

    for (int c = 0; c < NC; c++) {
        cp_wait<1>();
        __syncthreads();
        if (c + 2 < NC) fill(c + 2);
        cp_commit();

        const __half* Sb = sh + (c % KVSTG) * KVTILEH;
#pragma unroll
        for (int ks = 0; ks < 2; ks++) {
            const int kk = ks * 16 + 4 * tg;
            unsigned a[4], bb[4][2];
            {
                int base = (wm + g) * SPADH + kk;
                uint2 lo = *(const uint2*)&Sb[base];
                uint2 hi = *(const uint2*)&Sb[base + 8 * SPADH];
                a[0] = lo.x; a[1] = hi.x; a[2] = lo.y; a[3] = hi.y;
            }
#pragma unroll
            for (int nt = 0; nt < 4; nt++) {
                uint2 bv = *(const uint2*)&Sb[(64 + wn + nt * 8 + g) * SPADH + kk];
                bb[nt][0] = bv.x; bb[nt][1] = bv.y;
            }
#pragma unroll
            for (int nt = 0; nt < 4; nt++)
                mma_fp16(acc[nt], a, bb[nt]);
        }
        __syncthreads();
    }

    float* kvbh = kv + (size_t)bh * DHEAD * DHEAD;
    const int row0 = wm + g;
#pragma unroll
    for (int nt = 0; nt < 4; nt++) {
        int col = wn + nt * 8 + 2 * tg;
        atomicAdd(&kvbh[row0 * DHEAD + col],           acc[nt][0]);
        atomicAdd(&kvbh[row0 * DHEAD + col + 1],       acc[nt][1]);
        atomicAdd(&kvbh[(row0 + 8) * DHEAD + col],     acc[nt][2]);
        atomicAdd(&kvbh[(row0 + 8) * DHEAD + col + 1], acc[nt][3]);
    }

    {
        int j = tid >> 2;
        int q = tid & 3;
        const __half* kr = KtB + (size_t)j * S_LEN + q * 128;
        float s = 0.0f;
#pragma unroll
        for (int u = 0; u < 16; u++) {
            uint4 raw = *(const uint4*)&kr[u * 8];
            const __half2* hp = (const __half2*)&raw;
#pragma unroll
            for (int p = 0; p < 4; p++) {
                float2 f = __half22float2(hp[p]);
                s += f.x + f.y;
            }
        }
        s += __shfl_down_sync(0xFFFFFFFF, s, 1);
        s += __shfl_down_sync(0xFFFFFFFF, s, 2);
        if (q == 0) atomicAdd(&ksum[bh * DHEAD + j], s);
    }
}

// ---------------------------------------------------------------------------
// Tensor-core attention apply (R14 proven)
// ---------------------------------------------------------------------------
#define APAD 80
#define OPAD 72

__global__ void __launch_bounds__(128)
attn_mma_kernel(const __half* __restrict__ Qf, const float* __restrict__ kv,
                const float* __restrict__ ksum, __half* __restrict__ attn) {
    const int h  = blockIdx.y;
    const int t0 = blockIdx.x * 128;
    const int b  = t0 / S_LEN;
    const int bh = b * NHEADS + h;
    const int tid  = threadIdx.x;
    const int lane = tid & 31;
    const int warp = tid >> 5;
    const int g    = lane >> 2;
    const int tg   = lane & 3;
    const int wm   = warp * 32;

    __shared__ __half Qs[128 * APAD];
    __shared__ __half Bs[64 * APAD];
    __shared__ float  kss[64];
    __shared__ float  nrm[128];

#pragma unroll
    for (int i = 0; i < 8; i++) {
        int idx = tid + 128 * i;
        int r = idx >> 3, c8 = (idx & 7) * 8;
        *(uint4*)&Qs[r * APAD + c8] =
            *(const uint4*)&Qf[(size_t)(t0 + r) * DMODEL + h * DHEAD + c8];
    }
    const float* kvsrc = kv + (size_t)bh * DHEAD * DHEAD;
#pragma unroll
    for (int i = 0; i < 8; i++) {
        int idx = tid + 128 * i;
        int r = idx >> 4, c4 = (idx & 15) * 4;
        float4 v = *(const float4*)&kvsrc[r * DHEAD + c4];
        __half2* dst = (__half2*)&Bs[r * APAD + c4];
        dst[0] = __floats2half2_rn(v.x, v.y);
        dst[1] = __floats2half2_rn(v.z, v.w);
    }
    if (tid < 64) kss[tid] = ksum[bh * DHEAD + tid];
    __syncthreads();

    {
        float nd = 0.0f;
        const __half2* qr = (const __half2*)&Qs[tid * APAD];
#pragma unroll
        for (int j = 0; j < 32; j++) {
            float2 f = __half22float2(qr[j]);
            nd += f.x * kss[2 * j] + f.y * kss[2 * j + 1];
        }
        nrm[tid] = 1.0f / (nd + 1e-6f);
    }
    __syncthreads();

    float acc[2][8][4];
#pragma unroll
    for (int mt = 0; mt < 2; mt++)
#pragma unroll
        for (int nt = 0; nt < 8; nt++)
#pragma unroll
            for (int i = 0; i < 4; i++) acc[mt][nt][i] = 0.0f;

#pragma unroll
    for (int ks = 0; ks < 4; ks++) {
        const int kk = ks * 16 + 4 * tg;
        unsigned a[2][4], bb[8][2];
#pragma unroll
        for (int mt = 0; mt < 2; mt++) {
            int base = (wm + mt * 16 + g) * APAD + kk;
            uint2 lo = *(const uint2*)&Qs[base];
            uint2 hi = *(const uint2*)&Qs[base + 8 * APAD];
            a[mt][0] = lo.x; a[mt][1] = hi.x; a[mt][2] = lo.y; a[mt][3] = hi.y;
        }
#pragma unroll
        for (int nt = 0; nt < 8; nt++) {
            uint2 bv = *(const uint2*)&Bs[(nt * 8 + g) * APAD + kk];
            bb[nt][0] = bv.x; bb[nt][1] = bv.y;
        }
#pragma unroll
        for (int mt = 0; mt < 2; mt++)
#pragma unroll
            for (int nt = 0; nt < 8; nt++)
                mma_fp16(acc[mt][nt], a[mt], bb[nt]);
    }

    __syncthreads();
    __half* Os = Qs;
#pragma unroll
    for (int mt = 0; mt < 2; mt++) {
        int row0 = wm + mt * 16 + g;
        float n0 = nrm[row0];
        float n1 = nrm[row0 + 8];
#pragma unroll
        for (int nt = 0; nt < 8; nt++) {
            int col = nt * 8 + 2 * tg;
            *(__half2*)&Os[row0 * OPAD + col] =
                __floats2half2_rn(acc[mt][nt][0] * n0, acc[mt][nt][1] * n0);
            *(__half2*)&Os[(row0 + 8) * OPAD + col] =
                __floats2half2_rn(acc[mt][nt][2] * n1, acc[mt][nt][3] * n1);
        }
    }
    __syncthreads();

#pragma unroll
    for (int i = 0; i < 8; i++) {
        int idx = tid + 128 * i;
        int r = idx >> 3, c8 = (idx & 7) * 8;
        uint4 v = *(const uint4*)&Os[r * OPAD + c8];
        *(uint4*)&attn[(size_t)(t0 + r) * DMODEL + h * DHEAD + c8] = v;
    }
}

// ---------------------------------------------------------------------------
// Launch
// ---------------------------------------------------------------------------
extern "C" void kernel_launch(void* const* d_in, const int* in_sizes, int n_in,
                              void* d_out, int out_size) {
    const float* query = (const float*)d_in[0];
    const float* key_  = (const float*)d_in[1];
    const float* value = (const float*)d_in[2];
    const float* Wq = (const float*)d_in[3];
    const float* bq = (const float*)d_in[4];
    const float* Wk = (const float*)d_in[5];
    const float* bk = (const float*)d_in[6];
    const float* Wv = (const float*)d_in[7];
    const float* bv = (const float*)d_in[8];
    const float* Wo = (const float*)d_in[9];
    const float* bo = (const float*)d_in[10];
    float* out = (float*)d_out;

    float *kv, *ks;
    __half *hqf, *hkt, *hvt, *hq, *hk, *hv, *hattn, *hw;
    cudaGetSymbolAddress((void**)&kv,    g_kv);
    cudaGetSymbolAddress((void**)&ks,    g_ksum);
    cudaGetSymbolAddress((void**)&hqf,   g_hqf);
    cudaGetSymbolAddress((void**)&hkt,   g_hkt);
    cudaGetSymbolAddress((void**)&hvt,   g_hvt);
    cudaGetSymbolAddress((void**)&hq,    g_hq);
    cudaGetSymbolAddress((void**)&hk,    g_hk);
    cudaGetSymbolAddress((void**)&hv,    g_hv);
    cudaGetSymbolAddress((void**)&hattn, g_hattn);
    cudaGetSymbolAddress((void**)&hw,    g_hw);
    __half* hwq = hw;
    __half* hwk = hw + (size_t)DMODEL * DMODEL;
    __half* hwv = hw + (size_t)2 * DMODEL * DMODEL;
    __half* hwo = hw + (size_t)3 * DMODEL * DMODEL;

    static int smem_set = 0;
    if (!smem_set) {
        cudaFuncSetAttribute(gemm_fp16_kernel<1, 1>,
                             cudaFuncAttributeMaxDynamicSharedMemorySize, GEMM_SMEM_BYTES);
        cudaFuncSetAttribute(gemm_fp16_kernel<1, 2>,
                             cudaFuncAttributeMaxDynamicSharedMemorySize, GEMM_SMEM_BYTES);
        cudaFuncSetAttribute(gemm_fp16_kernel<0, 2>,
                             cudaFuncAttributeMaxDynamicSharedMemorySize, GEMM_SMEM_BYTES);
        cudaFuncSetAttribute(gemm_fp16_kernel<0, 0>,
                             cudaFuncAttributeMaxDynamicSharedMemorySize, GEMM_SMEM_BYTES);
        smem_set = 1;
    }

    // fp16 pre-rounding (2 launches: inputs x3, weights x4)
    const int N4_IN = (NROWS * DMODEL) / 4;
    const int N4_W  = (DMODEL * DMODEL) / 4;
    round3_fp16_kernel<<<dim3(N4_IN / 256, 3), 256>>>(query, hq, key_, hk, value, hv, N4_IN);
    round4_fp16_kernel<<<dim3(N4_W / 256, 4), 256>>>(Wq, hwq, Wk, hwk, Wv, hwv, Wo, hwo, N4_W);

    // zero accumulators for atomics
    zero_kernel<<<(BATCH * NHEADS * DHEAD * DHEAD + 255) / 256, 256>>>(kv, BATCH * NHEADS * DHEAD * DHEAD);
    zero_kernel<<<(BATCH * NHEADS * DHEAD + 255) / 256, 256>>>(ks, BATCH * NHEADS * DHEAD);

    dim3 gemm_grid(DMODEL / BN, NROWS / BM);  // (8, 256)
    gemm_fp16_kernel<1, 1><<<gemm_grid, 256, GEMM_SMEM_BYTES>>>(hq, hwq, bq, hqf);   // Q normal fp16
    gemm_fp16_kernel<1, 2><<<gemm_grid, 256, GEMM_SMEM_BYTES>>>(hk, hwk, bk, hkt);   // K transposed
    gemm_fp16_kernel<0, 2><<<gemm_grid, 256, GEMM_SMEM_BYTES>>>(hv, hwv, bv, hvt);   // V transposed

    kv_mma_kernel<<<dim3(BATCH * NHEADS, NSPLIT), 256>>>(hkt, hvt, kv, ks);

    attn_mma_kernel<<<dim3(NROWS / 128, NHEADS), 128>>>(hqf, kv, ks, hattn);

    gemm_fp16_kernel<0, 0><<<gemm_grid, 256, GEMM_SMEM_BYTES>>>(hattn, hwo, bo, out);
}

// round 17
// speedup vs baseline: 1.0244x; 1.0244x over previous
#include <cuda_runtime.h>
#include <cuda_fp16.h>
#include <math.h>
#include <stdint.h>

#define S_LEN   8192
#define BATCH   4
#define DMODEL  1024
#define NROWS   (BATCH * S_LEN)   // 32768
#define NHEADS  16
#define DHEAD   64

// Scratch (device globals: allocation-free per harness rules)
__device__ __half g_hqf[(size_t)NROWS * DMODEL];  // fp16 Q features (token-major)
__device__ __half g_hkt[(size_t)NROWS * DMODEL];  // fp16 K features TRANSPOSED [b*1024+feat][s]
__device__ __half g_hvt[(size_t)NROWS * DMODEL];  // fp16 V features TRANSPOSED
__device__ __half g_hq[(size_t)NROWS * DMODEL];   // fp16-rounded inputs
__device__ __half g_hk[(size_t)NROWS * DMODEL];
__device__ __half g_hv[(size_t)NROWS * DMODEL];
__device__ __half g_hattn[(size_t)NROWS * DMODEL];
__device__ __half g_hw[4][DMODEL * DMODEL];       // fp16-rounded weights
__device__ float  g_kv[BATCH * NHEADS * DHEAD * DHEAD];   // [b,h,dv,dk]
__device__ float  g_ksum[BATCH * NHEADS * DHEAD];

// ---------------------------------------------------------------------------
// helpers
// ---------------------------------------------------------------------------
__device__ __forceinline__ void mma_fp16(float* c, const unsigned* a, const unsigned* b) {
    asm volatile(
        "mma.sync.aligned.m16n8k16.row.col.f32.f16.f16.f32 "
        "{%0,%1,%2,%3}, {%4,%5,%6,%7}, {%8,%9}, {%0,%1,%2,%3};"
        : "+f"(c[0]), "+f"(c[1]), "+f"(c[2]), "+f"(c[3])
        : "r"(a[0]), "r"(a[1]), "r"(a[2]), "r"(a[3]), "r"(b[0]), "r"(b[1]));
}

__device__ __forceinline__ void cp_async16(unsigned smem_addr, const void* gptr) {
    asm volatile("cp.async.cg.shared.global [%0], [%1], 16;"
                 :: "r"(smem_addr), "l"(gptr));
}
__device__ __forceinline__ void cp_commit() {
    asm volatile("cp.async.commit_group;");
}
template <int N>
__device__ __forceinline__ void cp_wait() {
    asm volatile("cp.async.wait_group %0;" :: "n"(N));
}

// ---------------------------------------------------------------------------
// Merged fp16 rounding passes (blockIdx.y selects tensor)
// ---------------------------------------------------------------------------
__global__ void round3_fp16_kernel(const float* __restrict__ i0, __half* __restrict__ o0,
                                   const float* __restrict__ i1, __half* __restrict__ o1,
                                   const float* __restrict__ i2, __half* __restrict__ o2,
                                   int n4) {
    int i = blockIdx.x * blockDim.x + threadIdx.x;
    if (i >= n4) return;
    const float* in;
    __half* out;
    switch (blockIdx.y) {
        case 0:  in = i0; out = o0; break;
        case 1:  in = i1; out = o1; break;
        default: in = i2; out = o2; break;
    }
    float4 v = ((const float4*)in)[i];
    __half2* o = (__half2*)(out + (size_t)i * 4);
    o[0] = __floats2half2_rn(v.x, v.y);
    o[1] = __floats2half2_rn(v.z, v.w);
}

__global__ void round4_fp16_kernel(const float* __restrict__ i0, __half* __restrict__ o0,
                                   const float* __restrict__ i1, __half* __restrict__ o1,
                                   const float* __restrict__ i2, __half* __restrict__ o2,
                                   const float* __restrict__ i3, __half* __restrict__ o3,
                                   int n4) {
    int i = blockIdx.x * blockDim.x + threadIdx.x;
    if (i >= n4) return;
    const float* in;
    __half* out;
    switch (blockIdx.y) {
        case 0:  in = i0; out = o0; break;
        case 1:  in = i1; out = o1; break;
        case 2:  in = i2; out = o2; break;
        default: in = i3; out = o3; break;
    }
    float4 v = ((const float4*)in)[i];
    __half2* o = (__half2*)(out + (size_t)i * 4);
    o[0] = __floats2half2_rn(v.x, v.y);
    o[1] = __floats2half2_rn(v.z, v.w);
}

// zero two buffers in one launch
__global__ void zero2_kernel(float* a, int na, float* b, int nb) {
    int i = blockIdx.x * blockDim.x + threadIdx.x;
    if (i < na) a[i] = 0.0f;
    if (i < nb) b[i] = 0.0f;
}

// ---------------------------------------------------------------------------
// fp16 GEMM: C = A @ W^T + bias, optional elu+1.
// OUTMODE: 0 = fp32 token-major, 1 = fp16 token-major,
//          2 = fp16 TRANSPOSED: Ct[(b*1024 + col)][s], s contiguous
// 256 threads, 8 warps (2x4), warp tile 64x32, 4-stage cp.async pipeline,
// one barrier per k-chunk (R10/R16 schedule).
// ---------------------------------------------------------------------------
#define BM 128
#define BN 128
#define BKH 32                    // k halves per chunk
#define SPADH 48                  // halves per smem row (96B)
#define TILEH (BM * SPADH)        // 6144 halves = 12288 B
#define NSTAGE 4
#define GEMM_SMEM_BYTES (2 * NSTAGE * TILEH * 2)   // 98304 B
#define CPAD 130                  // halves per staging row

template <int EPI, int OUTMODE>
__global__ void __launch_bounds__(256, 2)
gemm_fp16_kernel(const __half* __restrict__ A, const __half* __restrict__ W,
                 const float* __restrict__ bias, void* __restrict__ Cv) {
    extern __shared__ __half sh[];            // [A0..A3, B0..B3]
    __half* Asm = sh;
    __half* Bsm = sh + NSTAGE * TILEH;

    const int tid  = threadIdx.x;
    const int lane = tid & 31;
    const int warp = tid >> 5;
    const int wm   = (warp & 1) * 64;
    const int wn   = (warp >> 1) * 32;
    const int m0   = blockIdx.y * BM;
    const int n0   = blockIdx.x * BN;
    const int g    = lane >> 2;
    const int tg   = lane & 3;

    unsigned sbase = (unsigned)__cvta_generic_to_shared(sh);

    float acc[4][4][4];
#pragma unroll
    for (int mt = 0; mt < 4; mt++)
#pragma unroll
        for (int nt = 0; nt < 4; nt++)
#pragma unroll
            for (int i = 0; i < 4; i++) acc[mt][nt][i] = 0.0f;

    const int r0  = tid >> 2;          // rows r0, r0+64
    const int kc  = (tid & 3) * 8;
    const __half* Ap = A + (size_t)(m0 + r0) * DMODEL + kc;
    const __half* Wp = W + (size_t)(n0 + r0) * DMODEL + kc;
    const unsigned a_d0 = sbase + (r0 * SPADH + kc) * 2;
    const unsigned a_d1 = sbase + ((r0 + 64) * SPADH + kc) * 2;
    const unsigned b_d0 = a_d0 + NSTAGE * TILEH * 2;
    const unsigned b_d1 = a_d1 + NSTAGE * TILEH * 2;

    const int NK = DMODEL / BKH;   // 32 chunks

    auto fill = [&](int c) {
        const unsigned so = (unsigned)(c % NSTAGE) * TILEH * 2;
        const __half* Apn = Ap + c * BKH;
        const __half* Wpn = Wp + c * BKH;
        cp_async16(a_d0 + so, Apn);
        cp_async16(a_d1 + so, Apn + (size_t)64 * DMODEL);
        cp_async16(b_d0 + so, Wpn);
        cp_async16(b_d1 + so, Wpn + (size_t)64 * DMODEL);
    };

    fill(0); cp_commit();
    fill(1); cp_commit();
    fill(2); cp_commit();

    for (int kt = 0; kt < NK; kt++) {
        cp_wait<2>();
        __syncthreads();

        if (kt + 3 < NK) fill(kt + 3);
        cp_commit();

        const int buf = kt % NSTAGE;
        const __half* Ab = Asm + buf * TILEH;
        const __half* Bb = Bsm + buf * TILEH;
#pragma unroll
        for (int ks = 0; ks < 2; ks++) {
            const int kk = ks * 16 + 4 * tg;
            unsigned a[4][4], b[4][2];
#pragma unroll
            for (int mt = 0; mt < 4; mt++) {
                int base = (wm + mt * 16 + g) * SPADH + kk;
                uint2 lo = *(const uint2*)&Ab[base];
                uint2 hi = *(const uint2*)&Ab[base + 8 * SPADH];
                a[mt][0] = lo.x; a[mt][1] = hi.x; a[mt][2] = lo.y; a[mt][3] = hi.y;
            }
#pragma unroll
            for (int nt = 0; nt < 4; nt++) {
                uint2 bb = *(const uint2*)&Bb[(wn + nt * 8 + g) * SPADH + kk];
                b[nt][0] = bb.x; b[nt][1] = bb.y;
            }
#pragma unroll
            for (int mt = 0; mt < 4; mt++)
#pragma unroll
                for (int nt = 0; nt < 4; nt++)
                    mma_fp16(acc[mt][nt], a[mt], b[nt]);
        }
    }

    if (OUTMODE == 2) __syncthreads();   // mainloop smem reads done before restaging

    // epilogue: bias + optional elu(x)+1
#pragma unroll
    for (int mt = 0; mt < 4; mt++) {
#pragma unroll
        for (int nt = 0; nt < 4; nt++) {
            int row = m0 + wm + mt * 16 + g;
            int col = n0 + wn + nt * 8 + 2 * tg;
            float bv0 = bias[col];
            float bv1 = bias[col + 1];
            float v00 = acc[mt][nt][0] + bv0;
            float v01 = acc[mt][nt][1] + bv1;
            float v10 = acc[mt][nt][2] + bv0;
            float v11 = acc[mt][nt][3] + bv1;
            if (EPI) {
                v00 = (v00 > 0.0f) ? v00 + 1.0f : expf(v00);
                v01 = (v01 > 0.0f) ? v01 + 1.0f : expf(v01);
                v10 = (v10 > 0.0f) ? v10 + 1.0f : expf(v10);
                v11 = (v11 > 0.0f) ? v11 + 1.0f : expf(v11);
            }
            if (OUTMODE == 0) {
                float* C = (float*)Cv;
                *(float2*)&C[(size_t)row * DMODEL + col]       = make_float2(v00, v01);
                *(float2*)&C[(size_t)(row + 8) * DMODEL + col] = make_float2(v10, v11);
            } else if (OUTMODE == 1) {
                __half* C = (__half*)Cv;
                *(__half2*)&C[(size_t)row * DMODEL + col]       = __floats2half2_rn(v00, v01);
                *(__half2*)&C[(size_t)(row + 8) * DMODEL + col] = __floats2half2_rn(v10, v11);
            } else {
                int lr = wm + mt * 16 + g;
                int lc = wn + nt * 8 + 2 * tg;
                *(__half2*)&sh[lr * CPAD + lc]       = __floats2half2_rn(v00, v01);
                *(__half2*)&sh[(lr + 8) * CPAD + lc] = __floats2half2_rn(v10, v11);
            }
        }
    }

    if (OUTMODE == 2) {
        __syncthreads();
        __half* Ct = (__half*)Cv;
        const int b    = m0 >> 13;        // m0 / 8192
        const int srow = m0 & 8191;
#pragma unroll
        for (int i = 0; i < 8; i++) {
            int slot = tid + 256 * i;
            int n  = slot & 127;
            int mb = slot >> 7;           // 0..15
            union { __half h[8]; uint4 u; } tmp;
#pragma unroll
            for (int j = 0; j < 8; j++)
                tmp.h[j] = sh[(mb * 8 + j) * CPAD + n];
            *(uint4*)&Ct[(size_t)(b * 1024 + n0 + n) * S_LEN + srow + mb * 8] = tmp.u;
        }
    }
}

// ---------------------------------------------------------------------------
// Tensor-core KV chain from TRANSPOSED features (R15 proven)
// ---------------------------------------------------------------------------
#define KVROWS 128
#define KVSTG 3
#define KVTILEH (KVROWS * SPADH)
#define NSPLIT 16

__global__ void __launch_bounds__(256)
kv_mma_kernel(const __half* __restrict__ Kt, const __half* __restrict__ Vt,
              float* __restrict__ kv, float* __restrict__ ksum) {
    __shared__ __half sh[KVSTG * KVTILEH];   // 36864 B

    const int bh = blockIdx.x;
    const int b  = bh >> 4;
    const int h  = bh & 15;
    const int s0 = blockIdx.y * (S_LEN / NSPLIT);
    const int tid  = threadIdx.x;
    const int lane = tid & 31;
    const int warp = tid >> 5;
    const int g    = lane >> 2;
    const int tg   = lane & 3;
    const int wm   = (warp & 3) * 16;
    const int wn   = (warp >> 2) * 32;

    const __half* VtB = Vt + (size_t)(b * 1024 + h * 64) * S_LEN + s0;
    const __half* KtB = Kt + (size_t)(b * 1024 + h * 64) * S_LEN + s0;

    unsigned sbase = (unsigned)__cvta_generic_to_shared(sh);

    const int fop  = tid >> 7;
    const int fidx = tid & 127;
    const __half* fb = fop ? KtB : VtB;

    auto fill = [&](int c) {
        const unsigned so = (unsigned)(c % KVSTG) * KVTILEH * 2;
#pragma unroll
        for (int i = 0; i < 2; i++) {
            int slot = fidx + 128 * i;
            int r  = slot >> 2;
            int kc = (slot & 3) * 8;
            cp_async16(sbase + so + ((fop * 64 + r) * SPADH + kc) * 2,
                       fb + (size_t)r * S_LEN + c * BKH + kc);
        }
    };

    float acc[4][4];
#pragma unroll
    for (int nt = 0; nt < 4; nt++)
#pragma unroll
        for (int i = 0; i < 4; i++) acc[nt][i] = 0.0f;

    const int NC = (S_LEN / NSPLIT) / BKH;   // 16 chunks
    fill(0); cp_commit();
    fill(1); cp_commit();

    for (int c = 0; c < NC; c++) {
        cp_wait<1>();
        __syncthreads();
        if (c + 2 < NC) fill(c + 2);
        cp_commit();

        const __half* Sb = sh + (c % KVSTG) * KVTILEH;
#pragma unroll
        for (int ks = 0; ks < 2; ks++) {
            const int kk = ks * 16 + 4 * tg;
            unsigned a[4], bb[4][2];
            {
                int base = (wm + g) * SPADH + kk;
                uint2 lo = *(const uint2*)&Sb[base];
                uint2 hi = *(const uint2*)&Sb[base + 8 * SPADH];
                a[0] = lo.x; a[1] = hi.x; a[2] = lo.y; a[3] = hi.y;
            }
#pragma unroll
            for (int nt = 0; nt < 4; nt++) {
                uint2 bv = *(const uint2*)&Sb[(64 + wn + nt * 8 + g) * SPADH + kk];
                bb[nt][0] = bv.x; bb[nt][1] = bv.y;
            }
#pragma unroll
            for (int nt = 0; nt < 4; nt++)
                mma_fp16(acc[nt], a, bb[nt]);
        }
        __syncthreads();
    }

    float* kvbh = kv + (size_t)bh * DHEAD * DHEAD;
    const int row0 = wm + g;
#pragma unroll
    for (int nt = 0; nt < 4; nt++) {
        int col = wn + nt * 8 + 2 * tg;
        atomicAdd(&kvbh[row0 * DHEAD + col],           acc[nt][0]);
        atomicAdd(&kvbh[row0 * DHEAD + col + 1],       acc[nt][1]);
        atomicAdd(&kvbh[(row0 + 8) * DHEAD + col],     acc[nt][2]);
        atomicAdd(&kvbh[(row0 + 8) * DHEAD + col + 1], acc[nt][3]);
    }

    {
        int j = tid >> 2;
        int q = tid & 3;
        const __half* kr = KtB + (size_t)j * S_LEN + q * 128;
        float s = 0.0f;
#pragma unroll
        for (int u = 0; u < 16; u++) {
            uint4 raw = *(const uint4*)&kr[u * 8];
            const __half2* hp = (const __half2*)&raw;
#pragma unroll
            for (int p = 0; p < 4; p++) {
                float2 f = __half22float2(hp[p]);
                s += f.x + f.y;
            }
        }
        s += __shfl_down_sync(0xFFFFFFFF, s, 1);
        s += __shfl_down_sync(0xFFFFFFFF, s, 2);
        if (q == 0) atomicAdd(&ksum[bh * DHEAD + j], s);
    }
}

// ---------------------------------------------------------------------------
// Tensor-core attention apply (R14 proven)
// ---------------------------------------------------------------------------
#define APAD 80
#define OPAD 72

__global__ void __launch_bounds__(128)
attn_mma_kernel(const __half* __restrict__ Qf, const float* __restrict__ kv,
                const float* __restrict__ ksum, __half* __restrict__ attn) {
    const int h  = blockIdx.y;
    const int t0 = blockIdx.x * 128;
    const int b  = t0 / S_LEN;
    const int bh = b * NHEADS + h;
    const int tid  = threadIdx.x;
    const int lane = tid & 31;
    const int warp = tid >> 5;
    const int g    = lane >> 2;
    const int tg   = lane & 3;
    const int wm   = warp * 32;

    __shared__ __half Qs[128 * APAD];
    __shared__ __half Bs[64 * APAD];
    __shared__ float  kss[64];
    __shared__ float  nrm[128];

#pragma unroll
    for (int i = 0; i < 8; i++) {
        int idx = tid + 128 * i;
        int r = idx >> 3, c8 = (idx & 7) * 8;
        *(uint4*)&Qs[r * APAD + c8] =
            *(const uint4*)&Qf[(size_t)(t0 + r) * DMODEL + h * DHEAD + c8];
    }
    const float* kvsrc = kv + (size_t)bh * DHEAD * DHEAD;
#pragma unroll
    for (int i = 0; i < 8; i++) {
        int idx = tid + 128 * i;
        int r = idx >> 4, c4 = (idx & 15) * 4;
        float4 v = *(const float4*)&kvsrc[r * DHEAD + c4];
        __half2* dst = (__half2*)&Bs[r * APAD + c4];
        dst[0] = __floats2half2_rn(v.x, v.y);
        dst[1] = __floats2half2_rn(v.z, v.w);
    }
    if (tid < 64) kss[tid] = ksum[bh * DHEAD + tid];
    __syncthreads();

    {
        float nd = 0.0f;
        const __half2* qr = (const __half2*)&Qs[tid * APAD];
#pragma unroll
        for (int j = 0; j < 32; j++) {
            float2 f = __half22float2(qr[j]);
            nd += f.x * kss[2 * j] + f.y * kss[2 * j + 1];
        }
        nrm[tid] = 1.0f / (nd + 1e-6f);
    }
    __syncthreads();

    float acc[2][8][4];
#pragma unroll
    for (int mt = 0; mt < 2; mt++)
#pragma unroll
        for (int nt = 0; nt < 8; nt++)
#pragma unroll
            for (int i = 0; i < 4; i++) acc[mt][nt][i] = 0.0f;

#pragma unroll
    for (int ks = 0; ks < 4; ks++) {
        const int kk = ks * 16 + 4 * tg;
        unsigned a[2][4], bb[8][2];
#pragma unroll
        for (int mt = 0; mt < 2; mt++) {
            int base = (wm + mt * 16 + g) * APAD + kk;
            uint2 lo = *(const uint2*)&Qs[base];
            uint2 hi = *(const uint2*)&Qs[base + 8 * APAD];
            a[mt][0] = lo.x; a[mt][1] = hi.x; a[mt][2] = lo.y; a[mt][3] = hi.y;
        }
#pragma unroll
        for (int nt = 0; nt < 8; nt++) {
            uint2 bv = *(const uint2*)&Bs[(nt * 8 + g) * APAD + kk];
            bb[nt][0] = bv.x; bb[nt][1] = bv.y;
        }
#pragma unroll
        for (int mt = 0; mt < 2; mt++)
#pragma unroll
            for (int nt = 0; nt < 8; nt++)
                mma_fp16(acc[mt][nt], a[mt], bb[nt]);
    }

    __syncthreads();
    __half* Os = Qs;
#pragma unroll
    for (int mt = 0; mt < 2; mt++) {
        int row0 = wm + mt * 16 + g;
        float n0 = nrm[row0];
        float n1 = nrm[row0 + 8];
#pragma unroll
        for (int nt = 0; nt < 8; nt++) {
            int col = nt * 8 + 2 * tg;
            *(__half2*)&Os[row0 * OPAD + col] =
                __floats2half2_rn(acc[mt][nt][0] * n0, acc[mt][nt][1] * n0);
            *(__half2*)&Os[(row0 + 8) * OPAD + col] =
                __floats2half2_rn(acc[mt][nt][2] * n1, acc[mt][nt][3] * n1);
        }
    }
    __syncthreads();

#pragma unroll
    for (int i = 0; i < 8; i++) {
        int idx = tid + 128 * i;
        int r = idx >> 3, c8 = (idx & 7) * 8;
        uint4 v = *(const uint4*)&Os[r * OPAD + c8];
        *(uint4*)&attn[(size_t)(t0 + r) * DMODEL + h * DHEAD + c8] = v;
    }
}

// ---------------------------------------------------------------------------
// Launch (fork-join across two streams; statics created on first,
// uncaptured, correctness call)
// ---------------------------------------------------------------------------
extern "C" void kernel_launch(void* const* d_in, const int* in_sizes, int n_in,
                              void* d_out, int out_size) {
    const float* query = (const float*)d_in[0];
    const float* key_  = (const float*)d_in[1];
    const float* value = (const float*)d_in[2];
    const float* Wq = (const float*)d_in[3];
    const float* bq = (const float*)d_in[4];
    const float* Wk = (const float*)d_in[5];
    const float* bk = (const float*)d_in[6];
    const float* Wv = (const float*)d_in[7];
    const float* bv = (const float*)d_in[8];
    const float* Wo = (const float*)d_in[9];
    const float* bo = (const float*)d_in[10];
    float* out = (float*)d_out;

    float *kv, *ks;
    __half *hqf, *hkt, *hvt, *hq, *hk, *hv, *hattn, *hw;
    cudaGetSymbolAddress((void**)&kv,    g_kv);
    cudaGetSymbolAddress((void**)&ks,    g_ksum);
    cudaGetSymbolAddress((void**)&hqf,   g_hqf);
    cudaGetSymbolAddress((void**)&hkt,   g_hkt);
    cudaGetSymbolAddress((void**)&hvt,   g_hvt);
    cudaGetSymbolAddress((void**)&hq,    g_hq);
    cudaGetSymbolAddress((void**)&hk,    g_hk);
    cudaGetSymbolAddress((void**)&hv,    g_hv);
    cudaGetSymbolAddress((void**)&hattn, g_hattn);
    cudaGetSymbolAddress((void**)&hw,    g_hw);
    __half* hwq = hw;
    __half* hwk = hw + (size_t)DMODEL * DMODEL;
    __half* hwv = hw + (size_t)2 * DMODEL * DMODEL;
    __half* hwo = hw + (size_t)3 * DMODEL * DMODEL;

    static cudaStream_t s1 = nullptr;
    static cudaEvent_t evFork = nullptr, evR = nullptr, evZ = nullptr, evQ = nullptr;
    if (!s1) {
        cudaStreamCreateWithFlags(&s1, cudaStreamNonBlocking);
        cudaEventCreateWithFlags(&evFork, cudaEventDisableTiming);
        cudaEventCreateWithFlags(&evR,    cudaEventDisableTiming);
        cudaEventCreateWithFlags(&evZ,    cudaEventDisableTiming);
        cudaEventCreateWithFlags(&evQ,    cudaEventDisableTiming);
        cudaFuncSetAttribute(gemm_fp16_kernel<1, 1>,
                             cudaFuncAttributeMaxDynamicSharedMemorySize, GEMM_SMEM_BYTES);
        cudaFuncSetAttribute(gemm_fp16_kernel<1, 2>,
                             cudaFuncAttributeMaxDynamicSharedMemorySize, GEMM_SMEM_BYTES);
        cudaFuncSetAttribute(gemm_fp16_kernel<0, 2>,
                             cudaFuncAttributeMaxDynamicSharedMemorySize, GEMM_SMEM_BYTES);
        cudaFuncSetAttribute(gemm_fp16_kernel<0, 0>,
                             cudaFuncAttributeMaxDynamicSharedMemorySize, GEMM_SMEM_BYTES);
    }

    const int N4_IN = (NROWS * DMODEL) / 4;
    const int N4_W  = (DMODEL * DMODEL) / 4;
    const int NKV   = BATCH * NHEADS * DHEAD * DHEAD;
    const int NKS   = BATCH * NHEADS * DHEAD;
    dim3 gemm_grid(DMODEL / BN, NROWS / BM);  // (8, 256)

    // fork: side stream zeros the accumulators while main stream rounds
    cudaEventRecord(evFork, 0);
    cudaStreamWaitEvent(s1, evFork, 0);
    zero2_kernel<<<(NKV + 255) / 256, 256, 0, s1>>>(kv, NKV, ks, NKS);
    cudaEventRecord(evZ, s1);

    round3_fp16_kernel<<<dim3(N4_IN / 256, 3), 256>>>(query, hq, key_, hk, value, hv, N4_IN);
    round4_fp16_kernel<<<dim3(N4_W / 256, 4), 256>>>(Wq, hwq, Wk, hwk, Wv, hwv, Wo, hwo, N4_W);
    cudaEventRecord(evR, 0);

    // side stream: Q-GEMM (independent of the kv chain)
    cudaStreamWaitEvent(s1, evR, 0);
    gemm_fp16_kernel<1, 1><<<gemm_grid, 256, GEMM_SMEM_BYTES, s1>>>(hq, hwq, bq, hqf);
    cudaEventRecord(evQ, s1);

    // main stream: K-GEMM, V-GEMM, kv chain
    gemm_fp16_kernel<1, 2><<<gemm_grid, 256, GEMM_SMEM_BYTES>>>(hk, hwk, bk, hkt);
    gemm_fp16_kernel<0, 2><<<gemm_grid, 256, GEMM_SMEM_BYTES>>>(hv, hwv, bv, hvt);
    cudaStreamWaitEvent(0, evZ, 0);
    kv_mma_kernel<<<dim3(BATCH * NHEADS, NSPLIT), 256>>>(hkt, hvt, kv, ks);

    // join: attn needs Q features + kv
    cudaStreamWaitEvent(0, evQ, 0);
    attn_mma_kernel<<<dim3(NROWS / 128, NHEADS), 128>>>(hqf, kv, ks, hattn);

    gemm_fp16_kernel<0, 0><<<gemm_grid, 256, GEMM_SMEM_BYTES>>>(hattn, hwo, bo, out);
}